// round 15
// baseline (speedup 1.0000x reference)
#include <cuda_runtime.h>
#include <cstdint>

// Problem constants
#define RR 4
#define ND 81
#define NB 4
#define NC 128
#define NH 96
#define NW 160

// Tile geometry (proven core)
#define TX 32
#define YB 4
#define PX 4
#define XG 8
#define NDY 9
#define NTHREADS 288
#define CCHUNK 8
#define NCHUNK 16
#define TGT_W 40
#define TGT_H 12
#define TGT_TILE (CCHUNK*TGT_H*TGT_W)    // 3840 floats
#define SRC_TILE (CCHUNK*YB*TX)          // 1024 floats
#define BUF_FLOATS (TGT_TILE + SRC_TILE) // 4864
#define BUF_BYTES (BUF_FLOATS*4)         // 19456
#define SMEM_BYTES (3*BUF_BYTES)         // 58368
#define NQUADS (BUF_FLOATS/4)            // 1216
#define MAXSLOTS 5
#define CBYTES (CCHUNK*NH*NW*4)

// Schedule:
//  k2 (launched FIRST): leftover tiles 444..479, 8-way channel split
//      -> 288 blocks, 16 channels (2 chunks) each, partials to scratch.
//  k1: 444 full tiles = 148 SMs x occ 3, one perfect wave; each block also
//      folds ~211 quads of the 8-way partial reduction into out at the end
//      (safe: k2 completed before k1 started, stream order).
#define K1_TILES 444
#define NLEFT 36
#define NPART 8
#define PART_STRIDE (NLEFT*ND*128)       // 373248 floats per partial
#define K3_QUADS (NLEFT*ND*YB*8)         // 93312 float4 outputs

__device__ float g_scratch[NPART * PART_STRIDE];   // ~12 MB static scratch

__device__ __forceinline__ int disp_index(int dyv, int dxv) {
    int ay = dyv < 0 ? -dyv : dyv;
    int ax = dxv < 0 ? -dxv : dxv;
    if ((ay | ax) == 0) return 0;
    if (ax == 0) return 1 + (ay - 1) * 20 + (dyv < 0 ? 0 : 1);
    if (ay == 0) return 1 + (ax - 1) * 20 + (dxv < 0 ? 2 : 3);
    int base = 1 + (ay - 1) * 20 + 4 + (ax - 1) * 4;
    if (dyv < 0 && dxv < 0) return base + 0;
    if (dyv > 0 && dxv > 0) return base + 1;
    if (dyv < 0 && dxv > 0) return base + 2;
    return base + 3;
}

__device__ __forceinline__ void cp_async16(uint32_t saddr, const void* gaddr, int sz) {
    asm volatile("cp.async.cg.shared.global [%0], [%1], 16, %2;\n"
                 :: "r"(saddr), "l"(gaddr), "r"(sz));
}
__device__ __forceinline__ void cp_commit() {
    asm volatile("cp.async.commit_group;\n" ::: "memory");
}

__device__ __forceinline__ void make_slots(int tid, int x0, int y0,
                                           uint32_t* goff, uint32_t& flags) {
    flags = 0;
#pragma unroll
    for (int k = 0; k < MAXSLOTS; k++) {
        int idx = tid + k * NTHREADS;
        goff[k] = 0;
        if (idx < NQUADS) {
            if (idx < TGT_TILE / 4) {
                int cc  = idx / (TGT_H * (TGT_W / 4));
                int rm  = idx % (TGT_H * (TGT_W / 4));
                int row = rm / (TGT_W / 4);
                int xq  = rm % (TGT_W / 4);
                int gy = y0 + row - RR;
                int gx = x0 + xq * 4 - RR;
                bool ok = ((unsigned)gy < NH) && ((unsigned)gx < NW);
                if (ok) goff[k] = (uint32_t)(((cc * NH + gy) * NW + gx) * 4);
                flags |= 1u << k;
                if (ok) flags |= 1u << (k + 8);
            } else {
                int q   = idx - TGT_TILE / 4;
                int cc  = q / (YB * TX / 4);
                int rm  = q % (YB * TX / 4);
                int ry  = rm / (TX / 4);
                int xq  = rm % (TX / 4);
                goff[k] = (uint32_t)(((cc * NH + y0 + ry) * NW + x0 + xq * 4) * 4);
                flags |= 1u << (k + 8);
            }
        }
    }
}

// ==== Kernel 2 (runs FIRST): 288 blocks (36 tiles x 8 groups) -> scratch ====
__global__ __launch_bounds__(NTHREADS, 3)
void costvol_k2(const float* __restrict__ src,
                const float* __restrict__ tgt) {
    extern __shared__ __align__(16) float sm[];   // 2 buffers used
    const int tid  = threadIdx.x;
    const int lt   = blockIdx.x >> 3;             // 0..35
    const int part = blockIdx.x & 7;              // 16-channel group

    const int rem = 84 + lt;                      // (444+lt)%120, b=3
    const int y0  = (rem / 5) * YB;
    const int x0  = (rem % 5) * TX;

    const char* srcB = (const char*)(src + (size_t)3 * NC * NH * NW)
                       + (size_t)part * 2 * CBYTES;
    const char* tgtB = (const char*)(tgt + (size_t)3 * NC * NH * NW)
                       + (size_t)part * 2 * CBYTES;

    uint32_t goff[MAXSLOTS];
    uint32_t flags;
    make_slots(tid, x0, y0, goff, flags);

    const uint32_t smem_base = (uint32_t)__cvta_generic_to_shared(&sm[0]);

    const int xg   = tid & (XG - 1);
    const int dyi  = (tid >> 3) % NDY;
    const int yr   = tid / (XG * NDY);
    const int dyv  = dyi - RR;
    const int trow = yr + dyi;
    const int t_off = trow * TGT_W + xg * PX;
    const int s_off = TGT_TILE + yr * TX + xg * PX;

    float acc[NDY][PX];
#pragma unroll
    for (int i = 0; i < NDY; i++)
#pragma unroll
        for (int p = 0; p < PX; p++) acc[i][p] = 0.0f;

    auto stage = [&](int bi) {
        const uint32_t bofs = (uint32_t)bi * BUF_BYTES;
#pragma unroll
        for (int k = 0; k < MAXSLOTS; k++) {
            if (k < MAXSLOTS - 1 || tid < NQUADS - (MAXSLOTS - 1) * NTHREADS) {
                const char* base = (flags >> k & 1) ? tgtB : srcB;
                int sz = (flags >> (k + 8) & 1) ? 16 : 0;
                cp_async16(smem_base + bofs + (uint32_t)(tid + k * NTHREADS) * 16,
                           base + goff[k], sz);
                goff[k] += CBYTES;
            }
        }
        cp_commit();
    };

    stage(0);   // chunk 0
    stage(1);   // chunk 1

#pragma unroll
    for (int ch = 0; ch < 2; ch++) {
        if (ch == 0)
            asm volatile("cp.async.wait_group 1;\n" ::: "memory");
        else
            asm volatile("cp.async.wait_group 0;\n" ::: "memory");
        __syncthreads();

        const float* bp = sm + ch * BUF_FLOATS;
        const float* tb = bp + t_off;
        const float* sb = bp + s_off;
#pragma unroll
        for (int cc = 0; cc < CCHUNK; cc++) {
            float4 s4 = *(const float4*)(sb + cc * (YB * TX));
            const float4* tq = (const float4*)(tb + cc * (TGT_H * TGT_W));
            float4 t0 = tq[0], t1 = tq[1], t2 = tq[2];
            float s[PX] = {s4.x, s4.y, s4.z, s4.w};
            float t[12] = {t0.x, t0.y, t0.z, t0.w,
                           t1.x, t1.y, t1.z, t1.w,
                           t2.x, t2.y, t2.z, t2.w};
#pragma unroll
            for (int dx = 0; dx < NDY; dx++)
#pragma unroll
                for (int p = 0; p < PX; p++)
                    acc[dx][p] = fmaf(s[p], t[dx + p], acc[dx][p]);
        }
    }

    // store partials: scratch[part][((lt*ND + d)*YB + yr)*32 + xg*4 ..]
    float* sc = g_scratch + (size_t)part * PART_STRIDE;
#pragma unroll
    for (int dx = 0; dx < NDY; dx++) {
        int d = disp_index(dyv, dx - RR);
        float* o = sc + (((size_t)lt * ND + d) * YB + yr) * 32 + xg * PX;
        *(float4*)o = make_float4(acc[dx][0], acc[dx][1], acc[dx][2], acc[dx][3]);
    }
}

// ============ Kernel 1: 444 full tiles + folded partial reduction ============
__global__ __launch_bounds__(NTHREADS, 3)
void costvol_k1(const float* __restrict__ src,
                const float* __restrict__ tgt,
                float* __restrict__ out) {
    extern __shared__ __align__(16) float sm[];
    const int tid = threadIdx.x;
    const int bid = blockIdx.x;
    const uint32_t smem_base = (uint32_t)__cvta_generic_to_shared(&sm[0]);

    const int b   = bid / 120;
    const int rem = bid % 120;
    const int y0  = (rem / 5) * YB;
    const int x0  = (rem % 5) * TX;

    const char* srcB = (const char*)(src + (size_t)b * NC * NH * NW);
    const char* tgtB = (const char*)(tgt + (size_t)b * NC * NH * NW);

    uint32_t goff[MAXSLOTS];
    uint32_t flags;
    make_slots(tid, x0, y0, goff, flags);

    const int xg   = tid & (XG - 1);
    const int dyi  = (tid >> 3) % NDY;
    const int yr   = tid / (XG * NDY);
    const int dyv  = dyi - RR;
    const int trow = yr + dyi;
    const int t_off = trow * TGT_W + xg * PX;
    const int s_off = TGT_TILE + yr * TX + xg * PX;

    float acc[NDY][PX];
#pragma unroll
    for (int i = 0; i < NDY; i++)
#pragma unroll
        for (int p = 0; p < PX; p++) acc[i][p] = 0.0f;

    auto stage = [&](int bi) {
        const uint32_t bofs = (uint32_t)bi * BUF_BYTES;
#pragma unroll
        for (int k = 0; k < MAXSLOTS; k++) {
            if (k < MAXSLOTS - 1 || tid < NQUADS - (MAXSLOTS - 1) * NTHREADS) {
                const char* base = (flags >> k & 1) ? tgtB : srcB;
                int sz = (flags >> (k + 8) & 1) ? 16 : 0;
                cp_async16(smem_base + bofs + (uint32_t)(tid + k * NTHREADS) * 16,
                           base + goff[k], sz);
                goff[k] += CBYTES;
            }
        }
        cp_commit();
    };

    stage(0);
    stage(1);

#pragma unroll 1
    for (int ch = 0; ch < NCHUNK; ch++) {
        if (ch + 2 < NCHUNK)
            asm volatile("cp.async.wait_group 1;\n" ::: "memory");
        else
            asm volatile("cp.async.wait_group 0;\n" ::: "memory");
        __syncthreads();

        const float* bp = sm + (ch % 3) * BUF_FLOATS;
        const float* tb = bp + t_off;
        const float* sb = bp + s_off;
#pragma unroll
        for (int cc = 0; cc < CCHUNK; cc++) {
            float4 s4 = *(const float4*)(sb + cc * (YB * TX));
            const float4* tq = (const float4*)(tb + cc * (TGT_H * TGT_W));
            float4 t0 = tq[0], t1 = tq[1], t2 = tq[2];
            float s[PX] = {s4.x, s4.y, s4.z, s4.w};
            float t[12] = {t0.x, t0.y, t0.z, t0.w,
                           t1.x, t1.y, t1.z, t1.w,
                           t2.x, t2.y, t2.z, t2.w};
#pragma unroll
            for (int dx = 0; dx < NDY; dx++)
#pragma unroll
                for (int p = 0; p < PX; p++)
                    acc[dx][p] = fmaf(s[p], t[dx + p], acc[dx][p]);
        }

        if (ch + 2 < NCHUNK)
            stage((ch + 2) % 3);
    }

    const float inv = 1.0f / 81.0f;
    const int y = y0 + yr;
#pragma unroll
    for (int dx = 0; dx < NDY; dx++) {
        int d = disp_index(dyv, dx - RR);
        float* o = out + ((((size_t)b * ND + d) * NH) + y) * NW + x0 + xg * PX;
        float4 v = make_float4(acc[dx][0] * inv, acc[dx][1] * inv,
                               acc[dx][2] * inv, acc[dx][3] * inv);
        *(float4*)o = v;
    }

    // ---- folded reduction of leftover partials (k2 finished before k1) ----
    {
        int q = bid + K1_TILES * tid;
        if (tid < 211 && q < K3_QUADS) {
            float4 r = make_float4(0.f, 0.f, 0.f, 0.f);
#pragma unroll
            for (int pp = 0; pp < NPART; pp++) {
                const float4 v = *(const float4*)(g_scratch
                                  + (size_t)pp * PART_STRIDE + (size_t)q * 4);
                r.x += v.x; r.y += v.y; r.z += v.z; r.w += v.w;
            }
            r.x *= inv; r.y *= inv; r.z *= inv; r.w *= inv;

            int xq = q & 7;
            int ry = (q >> 3) & 3;
            int d  = (q >> 5) % ND;
            int lt = q / (ND * 32);
            int rm = 84 + lt;
            int yy = (rm / 5) * YB + ry;
            int xx = (rm % 5) * TX + xq * 4;
            float* o = out + (((size_t)(3 * ND + d) * NH) + yy) * NW + xx;
            *(float4*)o = r;
        }
    }
}

extern "C" void kernel_launch(void* const* d_in, const int* in_sizes, int n_in,
                              void* d_out, int out_size) {
    const float* src = (const float*)d_in[0];
    const float* tgt = (const float*)d_in[1];
    float* out = (float*)d_out;

    cudaFuncSetAttribute(costvol_k1,
                         cudaFuncAttributeMaxDynamicSharedMemorySize, SMEM_BYTES);
    cudaFuncSetAttribute(costvol_k2,
                         cudaFuncAttributeMaxDynamicSharedMemorySize, SMEM_BYTES);

    costvol_k2<<<NLEFT * NPART, NTHREADS, SMEM_BYTES>>>(src, tgt);   // partials first
    costvol_k1<<<K1_TILES, NTHREADS, SMEM_BYTES>>>(src, tgt, out);   // wave + fold
}

// round 16
// speedup vs baseline: 1.0792x; 1.0792x over previous
#include <cuda_runtime.h>
#include <cstdint>

// Problem constants
#define RR 4
#define ND 81
#define NB 4
#define NC 128
#define NH 96
#define NW 160

// Tile geometry (proven core)
#define TX 32
#define YB 4
#define PX 4
#define XG 8
#define NDY 9
#define NTHREADS 288
#define CCHUNK 8
#define NCHUNK 16
#define TGT_W 40
#define TGT_H 12
#define TGT_TILE (CCHUNK*TGT_H*TGT_W)    // 3840 floats
#define SRC_TILE (CCHUNK*YB*TX)          // 1024 floats
#define BUF_FLOATS (TGT_TILE + SRC_TILE) // 4864
#define BUF_BYTES (BUF_FLOATS*4)         // 19456
#define SMEM_BYTES (3*BUF_BYTES)         // 58368
#define NQUADS (BUF_FLOATS/4)            // 1216
#define MAXSLOTS 5
#define CBYTES (CCHUNK*NH*NW*4)

// Schedule:
//  k2 (launched FIRST): leftover tiles 444..479, 8-way channel split
//      -> 288 blocks, 16 channels (2 chunks) each, partials to scratch.
//  k1: 444 full tiles = 148 SMs x occ 3, one perfect wave; each block also
//      folds a CONTIGUOUS run of 211 partial-quads into out at the end
//      (coalesced; safe: k2 completed before k1 started, stream order).
#define K1_TILES 444
#define NLEFT 36
#define NPART 8
#define PART_STRIDE (NLEFT*ND*128)       // 373248 floats per partial
#define K3_QUADS (NLEFT*ND*YB*8)         // 93312 float4 outputs
#define FOLD_PER_BLOCK 211               // 444*211 >= 93312

__device__ float g_scratch[NPART * PART_STRIDE];   // ~12 MB static scratch

__device__ __forceinline__ int disp_index(int dyv, int dxv) {
    int ay = dyv < 0 ? -dyv : dyv;
    int ax = dxv < 0 ? -dxv : dxv;
    if ((ay | ax) == 0) return 0;
    if (ax == 0) return 1 + (ay - 1) * 20 + (dyv < 0 ? 0 : 1);
    if (ay == 0) return 1 + (ax - 1) * 20 + (dxv < 0 ? 2 : 3);
    int base = 1 + (ay - 1) * 20 + 4 + (ax - 1) * 4;
    if (dyv < 0 && dxv < 0) return base + 0;
    if (dyv > 0 && dxv > 0) return base + 1;
    if (dyv < 0 && dxv > 0) return base + 2;
    return base + 3;
}

__device__ __forceinline__ void cp_async16(uint32_t saddr, const void* gaddr, int sz) {
    asm volatile("cp.async.cg.shared.global [%0], [%1], 16, %2;\n"
                 :: "r"(saddr), "l"(gaddr), "r"(sz));
}
__device__ __forceinline__ void cp_commit() {
    asm volatile("cp.async.commit_group;\n" ::: "memory");
}

__device__ __forceinline__ void make_slots(int tid, int x0, int y0,
                                           uint32_t* goff, uint32_t& flags) {
    flags = 0;
#pragma unroll
    for (int k = 0; k < MAXSLOTS; k++) {
        int idx = tid + k * NTHREADS;
        goff[k] = 0;
        if (idx < NQUADS) {
            if (idx < TGT_TILE / 4) {
                int cc  = idx / (TGT_H * (TGT_W / 4));
                int rm  = idx % (TGT_H * (TGT_W / 4));
                int row = rm / (TGT_W / 4);
                int xq  = rm % (TGT_W / 4);
                int gy = y0 + row - RR;
                int gx = x0 + xq * 4 - RR;
                bool ok = ((unsigned)gy < NH) && ((unsigned)gx < NW);
                if (ok) goff[k] = (uint32_t)(((cc * NH + gy) * NW + gx) * 4);
                flags |= 1u << k;
                if (ok) flags |= 1u << (k + 8);
            } else {
                int q   = idx - TGT_TILE / 4;
                int cc  = q / (YB * TX / 4);
                int rm  = q % (YB * TX / 4);
                int ry  = rm / (TX / 4);
                int xq  = rm % (TX / 4);
                goff[k] = (uint32_t)(((cc * NH + y0 + ry) * NW + x0 + xq * 4) * 4);
                flags |= 1u << (k + 8);
            }
        }
    }
}

// ==== Kernel 2 (runs FIRST): 288 blocks (36 tiles x 8 groups) -> scratch ====
__global__ __launch_bounds__(NTHREADS, 3)
void costvol_k2(const float* __restrict__ src,
                const float* __restrict__ tgt) {
    extern __shared__ __align__(16) float sm[];   // 2 buffers used
    const int tid  = threadIdx.x;
    const int lt   = blockIdx.x >> 3;             // 0..35
    const int part = blockIdx.x & 7;              // 16-channel group

    const int rem = 84 + lt;                      // (444+lt)%120, b=3
    const int y0  = (rem / 5) * YB;
    const int x0  = (rem % 5) * TX;

    const char* srcB = (const char*)(src + (size_t)3 * NC * NH * NW)
                       + (size_t)part * 2 * CBYTES;
    const char* tgtB = (const char*)(tgt + (size_t)3 * NC * NH * NW)
                       + (size_t)part * 2 * CBYTES;

    uint32_t goff[MAXSLOTS];
    uint32_t flags;
    make_slots(tid, x0, y0, goff, flags);

    const uint32_t smem_base = (uint32_t)__cvta_generic_to_shared(&sm[0]);

    const int xg   = tid & (XG - 1);
    const int dyi  = (tid >> 3) % NDY;
    const int yr   = tid / (XG * NDY);
    const int dyv  = dyi - RR;
    const int trow = yr + dyi;
    const int t_off = trow * TGT_W + xg * PX;
    const int s_off = TGT_TILE + yr * TX + xg * PX;

    float acc[NDY][PX];
#pragma unroll
    for (int i = 0; i < NDY; i++)
#pragma unroll
        for (int p = 0; p < PX; p++) acc[i][p] = 0.0f;

    auto stage = [&](int bi) {
        const uint32_t bofs = (uint32_t)bi * BUF_BYTES;
#pragma unroll
        for (int k = 0; k < MAXSLOTS; k++) {
            if (k < MAXSLOTS - 1 || tid < NQUADS - (MAXSLOTS - 1) * NTHREADS) {
                const char* base = (flags >> k & 1) ? tgtB : srcB;
                int sz = (flags >> (k + 8) & 1) ? 16 : 0;
                cp_async16(smem_base + bofs + (uint32_t)(tid + k * NTHREADS) * 16,
                           base + goff[k], sz);
                goff[k] += CBYTES;
            }
        }
        cp_commit();
    };

    stage(0);   // chunk 0
    stage(1);   // chunk 1

#pragma unroll
    for (int ch = 0; ch < 2; ch++) {
        if (ch == 0)
            asm volatile("cp.async.wait_group 1;\n" ::: "memory");
        else
            asm volatile("cp.async.wait_group 0;\n" ::: "memory");
        __syncthreads();

        const float* bp = sm + ch * BUF_FLOATS;
        const float* tb = bp + t_off;
        const float* sb = bp + s_off;
#pragma unroll
        for (int cc = 0; cc < CCHUNK; cc++) {
            float4 s4 = *(const float4*)(sb + cc * (YB * TX));
            const float4* tq = (const float4*)(tb + cc * (TGT_H * TGT_W));
            float4 t0 = tq[0], t1 = tq[1], t2 = tq[2];
            float s[PX] = {s4.x, s4.y, s4.z, s4.w};
            float t[12] = {t0.x, t0.y, t0.z, t0.w,
                           t1.x, t1.y, t1.z, t1.w,
                           t2.x, t2.y, t2.z, t2.w};
#pragma unroll
            for (int dx = 0; dx < NDY; dx++)
#pragma unroll
                for (int p = 0; p < PX; p++)
                    acc[dx][p] = fmaf(s[p], t[dx + p], acc[dx][p]);
        }
    }

    // store partials: scratch[part][((lt*ND + d)*YB + yr)*32 + xg*4 ..]
    float* sc = g_scratch + (size_t)part * PART_STRIDE;
#pragma unroll
    for (int dx = 0; dx < NDY; dx++) {
        int d = disp_index(dyv, dx - RR);
        float* o = sc + (((size_t)lt * ND + d) * YB + yr) * 32 + xg * PX;
        *(float4*)o = make_float4(acc[dx][0], acc[dx][1], acc[dx][2], acc[dx][3]);
    }
}

// ============ Kernel 1: 444 full tiles + coalesced folded reduction ============
__global__ __launch_bounds__(NTHREADS, 3)
void costvol_k1(const float* __restrict__ src,
                const float* __restrict__ tgt,
                float* __restrict__ out) {
    extern __shared__ __align__(16) float sm[];
    const int tid = threadIdx.x;
    const int bid = blockIdx.x;
    const uint32_t smem_base = (uint32_t)__cvta_generic_to_shared(&sm[0]);

    const int b   = bid / 120;
    const int rem = bid % 120;
    const int y0  = (rem / 5) * YB;
    const int x0  = (rem % 5) * TX;

    const char* srcB = (const char*)(src + (size_t)b * NC * NH * NW);
    const char* tgtB = (const char*)(tgt + (size_t)b * NC * NH * NW);

    uint32_t goff[MAXSLOTS];
    uint32_t flags;
    make_slots(tid, x0, y0, goff, flags);

    const int xg   = tid & (XG - 1);
    const int dyi  = (tid >> 3) % NDY;
    const int yr   = tid / (XG * NDY);
    const int dyv  = dyi - RR;
    const int trow = yr + dyi;
    const int t_off = trow * TGT_W + xg * PX;
    const int s_off = TGT_TILE + yr * TX + xg * PX;

    float acc[NDY][PX];
#pragma unroll
    for (int i = 0; i < NDY; i++)
#pragma unroll
        for (int p = 0; p < PX; p++) acc[i][p] = 0.0f;

    auto stage = [&](int bi) {
        const uint32_t bofs = (uint32_t)bi * BUF_BYTES;
#pragma unroll
        for (int k = 0; k < MAXSLOTS; k++) {
            if (k < MAXSLOTS - 1 || tid < NQUADS - (MAXSLOTS - 1) * NTHREADS) {
                const char* base = (flags >> k & 1) ? tgtB : srcB;
                int sz = (flags >> (k + 8) & 1) ? 16 : 0;
                cp_async16(smem_base + bofs + (uint32_t)(tid + k * NTHREADS) * 16,
                           base + goff[k], sz);
                goff[k] += CBYTES;
            }
        }
        cp_commit();
    };

    stage(0);
    stage(1);

#pragma unroll 1
    for (int ch = 0; ch < NCHUNK; ch++) {
        if (ch + 2 < NCHUNK)
            asm volatile("cp.async.wait_group 1;\n" ::: "memory");
        else
            asm volatile("cp.async.wait_group 0;\n" ::: "memory");
        __syncthreads();

        const float* bp = sm + (ch % 3) * BUF_FLOATS;
        const float* tb = bp + t_off;
        const float* sb = bp + s_off;
#pragma unroll
        for (int cc = 0; cc < CCHUNK; cc++) {
            float4 s4 = *(const float4*)(sb + cc * (YB * TX));
            const float4* tq = (const float4*)(tb + cc * (TGT_H * TGT_W));
            float4 t0 = tq[0], t1 = tq[1], t2 = tq[2];
            float s[PX] = {s4.x, s4.y, s4.z, s4.w};
            float t[12] = {t0.x, t0.y, t0.z, t0.w,
                           t1.x, t1.y, t1.z, t1.w,
                           t2.x, t2.y, t2.z, t2.w};
#pragma unroll
            for (int dx = 0; dx < NDY; dx++)
#pragma unroll
                for (int p = 0; p < PX; p++)
                    acc[dx][p] = fmaf(s[p], t[dx + p], acc[dx][p]);
        }

        if (ch + 2 < NCHUNK)
            stage((ch + 2) % 3);
    }

    const float inv = 1.0f / 81.0f;
    const int y = y0 + yr;
#pragma unroll
    for (int dx = 0; dx < NDY; dx++) {
        int d = disp_index(dyv, dx - RR);
        float* o = out + ((((size_t)b * ND + d) * NH) + y) * NW + x0 + xg * PX;
        float4 v = make_float4(acc[dx][0] * inv, acc[dx][1] * inv,
                               acc[dx][2] * inv, acc[dx][3] * inv);
        *(float4*)o = v;
    }

    // ---- folded reduction, CONTIGUOUS per block (coalesced LDG/STG) ----
    {
        int q = bid * FOLD_PER_BLOCK + tid;   // lanes -> consecutive quads
        if (tid < FOLD_PER_BLOCK && q < K3_QUADS) {
            float4 r = make_float4(0.f, 0.f, 0.f, 0.f);
#pragma unroll
            for (int pp = 0; pp < NPART; pp++) {
                const float4 v = *(const float4*)(g_scratch
                                  + (size_t)pp * PART_STRIDE + (size_t)q * 4);
                r.x += v.x; r.y += v.y; r.z += v.z; r.w += v.w;
            }
            r.x *= inv; r.y *= inv; r.z *= inv; r.w *= inv;

            int xq = q & 7;
            int ry = (q >> 3) & 3;
            int d  = (q >> 5) % ND;
            int lt = q / (ND * 32);
            int rm = 84 + lt;
            int yy = (rm / 5) * YB + ry;
            int xx = (rm % 5) * TX + xq * 4;
            float* o = out + (((size_t)(3 * ND + d) * NH) + yy) * NW + xx;
            *(float4*)o = r;
        }
    }
}

extern "C" void kernel_launch(void* const* d_in, const int* in_sizes, int n_in,
                              void* d_out, int out_size) {
    const float* src = (const float*)d_in[0];
    const float* tgt = (const float*)d_in[1];
    float* out = (float*)d_out;

    cudaFuncSetAttribute(costvol_k1,
                         cudaFuncAttributeMaxDynamicSharedMemorySize, SMEM_BYTES);
    cudaFuncSetAttribute(costvol_k2,
                         cudaFuncAttributeMaxDynamicSharedMemorySize, SMEM_BYTES);

    costvol_k2<<<NLEFT * NPART, NTHREADS, SMEM_BYTES>>>(src, tgt);   // partials first
    costvol_k1<<<K1_TILES, NTHREADS, SMEM_BYTES>>>(src, tgt, out);   // wave + fold
}